// round 1
// baseline (speedup 1.0000x reference)
#include <cuda_runtime.h>
#include <math.h>

#define BATCH 16
#define SEQ   1024
#define EDIM  512
#define NROWS (BATCH*SEQ)              // 16384
#define TOTAL ((double)BATCH*SEQ*SEQ)  // 16777216
#define TEMP  13.544f
#define EPSV  1e-5

#define BM 128
#define BN 128
#define BKK 16

__device__ float  g_sq[NROWS];
__device__ double g_sum;
__device__ double g_sumsq;
__device__ float  g_coef;

// ---------------------------------------------------------------------------
// Kernel 1: per-row squared norms; block 0 thread 0 also resets accumulators
// (safe: accumulators are only consumed by later kernels in stream order).
// ---------------------------------------------------------------------------
__global__ void sq_kernel(const float* __restrict__ x) {
    if (blockIdx.x == 0 && threadIdx.x == 0) { g_sum = 0.0; g_sumsq = 0.0; }
    int gwarp = (blockIdx.x * blockDim.x + threadIdx.x) >> 5;
    int lane  = threadIdx.x & 31;
    if (gwarp >= NROWS) return;
    const float4* row = (const float4*)(x + (size_t)gwarp * EDIM);
    float s = 0.f;
    #pragma unroll
    for (int i = 0; i < 4; i++) {
        float4 v = row[lane + 32 * i];
        s += v.x*v.x + v.y*v.y + v.z*v.z + v.w*v.w;
    }
    #pragma unroll
    for (int o = 16; o > 0; o >>= 1) s += __shfl_xor_sync(0xffffffffu, s, o);
    if (lane == 0) g_sq[gwarp] = s;
}

// ---------------------------------------------------------------------------
// Kernel 2: batched X·X^T tile (128x128, BK=16, 8x8 micro-tile), fused
// epilogue: d = max(sq_i + sq_j - 2*gram, 0) written in-place to d_out,
// plus double-precision block reduction of sum(d), sum(d^2) -> atomics.
// ---------------------------------------------------------------------------
__global__ __launch_bounds__(256, 2)
void gram_kernel(const float* __restrict__ x, float* __restrict__ dout) {
    __shared__ float As[BKK][BM];
    __shared__ float Bs[BKK][BN];
    __shared__ float sqA[BM];
    __shared__ float sqB[BN];
    __shared__ double redS[8];
    __shared__ double redQ[8];

    const int b    = blockIdx.z;
    const int row0 = blockIdx.y * BM;
    const int col0 = blockIdx.x * BN;
    const float* Xb = x + (size_t)b * SEQ * EDIM;

    const int tid = threadIdx.x;
    const int tx  = tid & 15;
    const int ty  = tid >> 4;

    if (tid < 128)      sqA[tid]       = g_sq[b * SEQ + row0 + tid];
    else                sqB[tid - 128] = g_sq[b * SEQ + col0 + (tid - 128)];

    float acc[8][8];
    #pragma unroll
    for (int i = 0; i < 8; i++)
        #pragma unroll
        for (int j = 0; j < 8; j++) acc[i][j] = 0.f;

    for (int k0 = 0; k0 < EDIM; k0 += BKK) {
        #pragma unroll
        for (int i = 0; i < 2; i++) {
            int idx = tid * 2 + i;       // 0..511
            int r   = idx >> 2;          // 0..127
            int c   = (idx & 3) * 4;     // 0,4,8,12
            float4 va = *(const float4*)(Xb + (size_t)(row0 + r) * EDIM + k0 + c);
            As[c + 0][r] = va.x; As[c + 1][r] = va.y;
            As[c + 2][r] = va.z; As[c + 3][r] = va.w;
            float4 vb = *(const float4*)(Xb + (size_t)(col0 + r) * EDIM + k0 + c);
            Bs[c + 0][r] = vb.x; Bs[c + 1][r] = vb.y;
            Bs[c + 2][r] = vb.z; Bs[c + 3][r] = vb.w;
        }
        __syncthreads();

        #pragma unroll
        for (int k = 0; k < BKK; k++) {
            float a[8], bb[8];
            *(float4*)(a)      = *(const float4*)&As[k][ty * 4];
            *(float4*)(a + 4)  = *(const float4*)&As[k][ty * 4 + 64];
            *(float4*)(bb)     = *(const float4*)&Bs[k][tx * 4];
            *(float4*)(bb + 4) = *(const float4*)&Bs[k][tx * 4 + 64];
            #pragma unroll
            for (int i = 0; i < 8; i++)
                #pragma unroll
                for (int j = 0; j < 8; j++)
                    acc[i][j] += a[i] * bb[j];
        }
        __syncthreads();
    }

    // Epilogue: d = max(sq_i + sq_j - 2*gram, 0), write + accumulate stats
    double lsum = 0.0, lsq = 0.0;
    float* Db = dout + (size_t)b * SEQ * SEQ;
    #pragma unroll
    for (int i = 0; i < 8; i++) {
        int r = ty * 4 + (i & 3) + ((i >> 2) << 6);
        float sr = sqA[r];
        float o[8];
        #pragma unroll
        for (int j = 0; j < 8; j++) {
            int c = tx * 4 + (j & 3) + ((j >> 2) << 6);
            float d = sr + sqB[c] - 2.f * acc[i][j];
            d = fmaxf(d, 0.f);
            o[j] = d;
            lsum += (double)d;
            lsq  += (double)d * (double)d;
        }
        float* rp = Db + (size_t)(row0 + r) * SEQ + col0;
        *(float4*)(rp + tx * 4)      = *(float4*)&o[0];
        *(float4*)(rp + tx * 4 + 64) = *(float4*)&o[4];
    }

    // block reduction of doubles
    #pragma unroll
    for (int o = 16; o > 0; o >>= 1) {
        lsum += __shfl_xor_sync(0xffffffffu, lsum, o);
        lsq  += __shfl_xor_sync(0xffffffffu, lsq, o);
    }
    int w = tid >> 5, ln = tid & 31;
    if (ln == 0) { redS[w] = lsum; redQ[w] = lsq; }
    __syncthreads();
    if (tid < 32) {
        double s = (tid < 8) ? redS[tid] : 0.0;
        double q = (tid < 8) ? redQ[tid] : 0.0;
        #pragma unroll
        for (int o = 4; o > 0; o >>= 1) {
            s += __shfl_xor_sync(0xffffffffu, s, o);
            q += __shfl_xor_sync(0xffffffffu, q, o);
        }
        if (tid == 0) { atomicAdd(&g_sum, s); atomicAdd(&g_sumsq, q); }
    }
}

// ---------------------------------------------------------------------------
// Kernel 3: finalize statistics -> softmax coefficient
// logit_j = -(d_j - mean)*rstd*gamma/TEMP = coef*d_j + const (const cancels)
// ---------------------------------------------------------------------------
__global__ void finalize_kernel(const float* __restrict__ gamma) {
    double mean = g_sum / TOTAL;
    double var  = g_sumsq / TOTAL - mean * mean;
    double rstd = 1.0 / sqrt(var + EPSV);
    g_coef = (float)(-(double)gamma[0] * rstd / (double)TEMP);
}

// ---------------------------------------------------------------------------
// Kernel 4: in-place row softmax of coef*d. One block of 256 per row.
// ---------------------------------------------------------------------------
__global__ __launch_bounds__(256)
void softmax_kernel(float* __restrict__ dout) {
    __shared__ float red[8];
    size_t base = (size_t)blockIdx.x * SEQ;
    float coef = g_coef;
    int tid = threadIdx.x;

    float4 v = *(float4*)(dout + base + tid * 4);
    float t0 = coef * v.x, t1 = coef * v.y, t2 = coef * v.z, t3 = coef * v.w;

    float m = fmaxf(fmaxf(t0, t1), fmaxf(t2, t3));
    #pragma unroll
    for (int o = 16; o > 0; o >>= 1) m = fmaxf(m, __shfl_xor_sync(0xffffffffu, m, o));
    if ((tid & 31) == 0) red[tid >> 5] = m;
    __syncthreads();
    float bm = red[0];
    #pragma unroll
    for (int i = 1; i < 8; i++) bm = fmaxf(bm, red[i]);

    float e0 = __expf(t0 - bm), e1 = __expf(t1 - bm);
    float e2 = __expf(t2 - bm), e3 = __expf(t3 - bm);
    float s = e0 + e1 + e2 + e3;
    #pragma unroll
    for (int o = 16; o > 0; o >>= 1) s += __shfl_xor_sync(0xffffffffu, s, o);
    __syncthreads();
    if ((tid & 31) == 0) red[tid >> 5] = s;
    __syncthreads();
    float bs = 0.f;
    #pragma unroll
    for (int i = 0; i < 8; i++) bs += red[i];
    float inv = 1.f / bs;

    float4 o4 = make_float4(e0 * inv, e1 * inv, e2 * inv, e3 * inv);
    *(float4*)(dout + base + tid * 4) = o4;
}

// ---------------------------------------------------------------------------
extern "C" void kernel_launch(void* const* d_in, const int* in_sizes, int n_in,
                              void* d_out, int out_size) {
    const float* x     = (const float*)d_in[0];
    const float* gamma = (const float*)d_in[1];
    float* out = (float*)d_out;

    sq_kernel<<<NROWS * 32 / 256, 256>>>(x);
    dim3 grid(SEQ / BN, SEQ / BM, BATCH);
    gram_kernel<<<grid, 256>>>(x, out);
    finalize_kernel<<<1, 1>>>(gamma);
    softmax_kernel<<<NROWS, 256>>>(out);
}

// round 3
// speedup vs baseline: 2.0917x; 2.0917x over previous
#include <cuda_runtime.h>
#include <cuda_bf16.h>
#include <cstdint>
#include <math.h>

#define BATCH 16
#define SEQ   1024
#define EDIM  512
#define NROWS (BATCH*SEQ)
#define TOTALD ((double)BATCH*SEQ*SEQ)
#define TEMP  13.544f
#define EPSV  1e-5

// ---------------- device scratch (no allocations allowed) ------------------
__device__ __nv_bfloat16 g_hi[(size_t)NROWS * EDIM];   // 16 MB
__device__ __nv_bfloat16 g_lo[(size_t)NROWS * EDIM];   // 16 MB
__device__ float  g_sq[NROWS];
__device__ double g_sum;
__device__ double g_sumsq;
__device__ float  g_coef;

// ---------------- PTX helpers (base sm_90-era only; no 'a' features) -------
__device__ __forceinline__ uint32_t smem_u32(const void* p) {
    uint32_t a;
    asm("{ .reg .u64 t; cvta.to.shared.u64 t, %1; cvt.u32.u64 %0, t; }" : "=r"(a) : "l"(p));
    return a;
}
__device__ __forceinline__ void cp16(uint32_t dst, const void* src) {
    asm volatile("cp.async.cg.shared.global [%0], [%1], 16;" :: "r"(dst), "l"(src));
}
#define CP_COMMIT() asm volatile("cp.async.commit_group;" ::: "memory")
#define CP_WAIT(n)  asm volatile("cp.async.wait_group %0;" :: "n"(n) : "memory")

__device__ __forceinline__ void ldm4(uint32_t* r, uint32_t addr) {
    asm volatile("ldmatrix.sync.aligned.m8n8.x4.shared.b16 {%0,%1,%2,%3}, [%4];"
                 : "=r"(r[0]), "=r"(r[1]), "=r"(r[2]), "=r"(r[3]) : "r"(addr));
}
__device__ __forceinline__ void mma16816(float* c, const uint32_t* a,
                                         uint32_t b0, uint32_t b1) {
    asm volatile("mma.sync.aligned.m16n8k16.row.col.f32.bf16.bf16.f32 "
                 "{%0,%1,%2,%3}, {%4,%5,%6,%7}, {%8,%9}, {%0,%1,%2,%3};"
                 : "+f"(c[0]), "+f"(c[1]), "+f"(c[2]), "+f"(c[3])
                 : "r"(a[0]), "r"(a[1]), "r"(a[2]), "r"(a[3]), "r"(b0), "r"(b1));
}

// ---------------- gram kernel geometry -------------------------------------
#define KC        32                       // k elems per chunk
#define NCHUNK    (EDIM / KC)              // 16
#define TROWB     80                       // bytes per smem tile row (40 bf16, padded)
#define TILE_B    (128 * TROWB)            // 10240 bytes
#define NTILES    4                        // Ahi, Alo, Bhi, Blo
#define BUF_B     (NTILES * TILE_B)        // 40960
#define SM_SQA    0
#define SM_SQB    512
#define SM_RED    1024                     // 4 doubles sum
#define SM_REDQ   1056                     // 4 doubles sumsq
#define SM_TILES  2048
#define GRAM_SMEM (SM_TILES + 2 * BUF_B)   // 83968

// ---------------------------------------------------------------------------
// Kernel 1: fp32 -> (hi, lo) bf16 split + per-row squared norms.
// ---------------------------------------------------------------------------
__global__ __launch_bounds__(256)
void conv_kernel(const float* __restrict__ x) {
    if (blockIdx.x == 0 && threadIdx.x == 0) { g_sum = 0.0; g_sumsq = 0.0; }
    int gw   = (blockIdx.x * blockDim.x + threadIdx.x) >> 5;
    int lane = threadIdx.x & 31;
    if (gw >= NROWS) return;
    const float4* row = (const float4*)(x + (size_t)gw * EDIM);
    __nv_bfloat162* hi = (__nv_bfloat162*)(g_hi + (size_t)gw * EDIM);
    __nv_bfloat162* lo = (__nv_bfloat162*)(g_lo + (size_t)gw * EDIM);
    float s = 0.f;
    #pragma unroll
    for (int i = 0; i < 4; i++) {
        int e = lane + 32 * i;
        float4 v = row[e];
        s += v.x*v.x + v.y*v.y + v.z*v.z + v.w*v.w;
        __nv_bfloat16 hx = __float2bfloat16_rn(v.x), hy = __float2bfloat16_rn(v.y);
        __nv_bfloat16 hz = __float2bfloat16_rn(v.z), hw = __float2bfloat16_rn(v.w);
        __nv_bfloat162 h0; h0.x = hx; h0.y = hy;
        __nv_bfloat162 h1; h1.x = hz; h1.y = hw;
        __nv_bfloat162 l0, l1;
        l0.x = __float2bfloat16_rn(v.x - __bfloat162float(hx));
        l0.y = __float2bfloat16_rn(v.y - __bfloat162float(hy));
        l1.x = __float2bfloat16_rn(v.z - __bfloat162float(hz));
        l1.y = __float2bfloat16_rn(v.w - __bfloat162float(hw));
        hi[e * 2] = h0; hi[e * 2 + 1] = h1;
        lo[e * 2] = l0; lo[e * 2 + 1] = l1;
    }
    #pragma unroll
    for (int o = 16; o > 0; o >>= 1) s += __shfl_xor_sync(0xffffffffu, s, o);
    if (lane == 0) g_sq[gw] = s;
}

// ---------------------------------------------------------------------------
// Kernel 2: Gram 128x128 tile via mma.sync bf16 split (3 terms), cp.async
// double-buffered. 4 warps, each 64x64 output.
// Fused epilogue: d = max(sqI + sqJ - 2g, 0) -> out, + stats.
// ---------------------------------------------------------------------------
__device__ __forceinline__ void prefetch_chunk(
    const __nv_bfloat16* Ahi, const __nv_bfloat16* Alo,
    const __nv_bfloat16* Bhi, const __nv_bfloat16* Blo,
    uint32_t sb, int buf, int kc, int tid)
{
    const __nv_bfloat16* panels[NTILES] = { Ahi, Alo, Bhi, Blo };
    int w = tid >> 5, lane = tid & 31;
    const char* src = (const char*)panels[w] + kc * (KC * 2);
    uint32_t tb = sb + SM_TILES + buf * BUF_B + w * TILE_B;
    #pragma unroll
    for (int i = 0; i < 16; i++) {
        int idx = i * 32 + lane;         // 0..511
        int row = idx >> 2;              // 0..127
        int q   = idx & 3;               // 16B granule
        cp16(tb + row * TROWB + q * 16,
             src + (size_t)row * (EDIM * 2) + q * 16);
    }
}

__global__ __launch_bounds__(128, 2)
void gram_tc_kernel(float* __restrict__ dout) {
    extern __shared__ char smem[];
    const uint32_t sb = smem_u32(smem);
    const int tid  = threadIdx.x;
    const int wid  = tid >> 5;
    const int lane = tid & 31;

    const int b    = blockIdx.z;
    const int row0 = blockIdx.y * 128;
    const int col0 = blockIdx.x * 128;
    const int warp_m = (wid >> 1) * 64;
    const int warp_n = (wid & 1) * 64;

    const __nv_bfloat16* Ahi = g_hi + ((size_t)(b * SEQ + row0)) * EDIM;
    const __nv_bfloat16* Alo = g_lo + ((size_t)(b * SEQ + row0)) * EDIM;
    const __nv_bfloat16* Bhi = g_hi + ((size_t)(b * SEQ + col0)) * EDIM;
    const __nv_bfloat16* Blo = g_lo + ((size_t)(b * SEQ + col0)) * EDIM;

    // sq values into smem
    if (tid < 128) {
        ((float*)(smem + SM_SQA))[tid] = g_sq[b * SEQ + row0 + tid];
        ((float*)(smem + SM_SQB))[tid] = g_sq[b * SEQ + col0 + tid];
    }

    float acc[4][8][4];
    #pragma unroll
    for (int mi = 0; mi < 4; mi++)
        #pragma unroll
        for (int ni = 0; ni < 8; ni++)
            #pragma unroll
            for (int k = 0; k < 4; k++) acc[mi][ni][k] = 0.f;

    // per-lane ldmatrix address offsets (within a tile)
    // A x4: rows (lane&15), k halves by lane>>4
    const uint32_t aOff = (uint32_t)((warp_m + (lane & 15)) * TROWB + (lane >> 4) * 16);
    // B x4: rows (lane&7) + ((lane>>4)<<3), k half by (lane>>3)&1
    const uint32_t bOff = (uint32_t)((warp_n + (lane & 7) + ((lane >> 4) << 3)) * TROWB
                                     + ((lane >> 3) & 1) * 16);

    prefetch_chunk(Ahi, Alo, Bhi, Blo, sb, 0, 0, tid);
    CP_COMMIT();

    #pragma unroll 1
    for (int c = 0; c < NCHUNK; c++) {
        if (c + 1 < NCHUNK) {
            prefetch_chunk(Ahi, Alo, Bhi, Blo, sb, (c + 1) & 1, c + 1, tid);
            CP_COMMIT();
            CP_WAIT(1);
        } else {
            CP_WAIT(0);
        }
        __syncthreads();

        uint32_t base = sb + SM_TILES + (c & 1) * BUF_B;
        #pragma unroll
        for (int ks = 0; ks < 2; ks++) {
            const uint32_t kb = ks * 32;   // 16 bf16 = 32 bytes
            uint32_t aH[16], aL[16], bb[16];
            #pragma unroll
            for (int mi = 0; mi < 4; mi++) {
                ldm4(&aH[mi * 4], base + 0 * TILE_B + aOff + mi * 16 * TROWB + kb);
                ldm4(&aL[mi * 4], base + 1 * TILE_B + aOff + mi * 16 * TROWB + kb);
            }
            #pragma unroll
            for (int nj = 0; nj < 4; nj++)
                ldm4(&bb[nj * 4], base + 2 * TILE_B + bOff + nj * 16 * TROWB + kb);
            // hi*hi and lo*hi
            #pragma unroll
            for (int mi = 0; mi < 4; mi++)
                #pragma unroll
                for (int ni = 0; ni < 8; ni++) {
                    mma16816(acc[mi][ni], &aH[mi * 4], bb[ni * 2], bb[ni * 2 + 1]);
                    mma16816(acc[mi][ni], &aL[mi * 4], bb[ni * 2], bb[ni * 2 + 1]);
                }
            // hi*lo
            #pragma unroll
            for (int nj = 0; nj < 4; nj++)
                ldm4(&bb[nj * 4], base + 3 * TILE_B + bOff + nj * 16 * TROWB + kb);
            #pragma unroll
            for (int mi = 0; mi < 4; mi++)
                #pragma unroll
                for (int ni = 0; ni < 8; ni++)
                    mma16816(acc[mi][ni], &aH[mi * 4], bb[ni * 2], bb[ni * 2 + 1]);
        }
        __syncthreads();
    }

    // ---------------- epilogue -------------------------------------------
    const int g  = lane >> 2;
    const int t4 = lane & 3;
    const float* sqA = (const float*)(smem + SM_SQA);
    const float* sqB = (const float*)(smem + SM_SQB);
    float* Db = dout + (size_t)b * SEQ * SEQ;
    float fsum = 0.f, fsq = 0.f;
    #pragma unroll
    for (int mi = 0; mi < 4; mi++) {
        #pragma unroll
        for (int h = 0; h < 2; h++) {
            int rl = warp_m + mi * 16 + g + h * 8;
            float sr = sqA[rl];
            float* rp = Db + (size_t)(row0 + rl) * SEQ + col0;
            #pragma unroll
            for (int ni = 0; ni < 8; ni++) {
                int cl = warp_n + ni * 8 + t4 * 2;
                float d0 = fmaxf(sr + sqB[cl]     - 2.f * acc[mi][ni][2 * h],     0.f);
                float d1 = fmaxf(sr + sqB[cl + 1] - 2.f * acc[mi][ni][2 * h + 1], 0.f);
                fsum += d0 + d1;
                fsq  += d0 * d0 + d1 * d1;
                float2 o; o.x = d0; o.y = d1;
                *(float2*)(rp + cl) = o;
            }
        }
    }

    // stats reduction: warp fp32 -> per-warp double -> CTA -> atomics
    #pragma unroll
    for (int o = 16; o > 0; o >>= 1) {
        fsum += __shfl_xor_sync(0xffffffffu, fsum, o);
        fsq  += __shfl_xor_sync(0xffffffffu, fsq,  o);
    }
    if (lane == 0) {
        ((double*)(smem + SM_RED))[wid]  = (double)fsum;
        ((double*)(smem + SM_REDQ))[wid] = (double)fsq;
    }
    __syncthreads();
    if (tid == 0) {
        double s = 0.0, q = 0.0;
        #pragma unroll
        for (int k = 0; k < 4; k++) {
            s += ((double*)(smem + SM_RED))[k];
            q += ((double*)(smem + SM_REDQ))[k];
        }
        atomicAdd(&g_sum, s);
        atomicAdd(&g_sumsq, q);
    }
}

// ---------------------------------------------------------------------------
// Kernel 3: finalize -> softmax coefficient (mean/beta cancel in softmax)
// ---------------------------------------------------------------------------
__global__ void finalize_kernel(const float* __restrict__ gamma) {
    double mean = g_sum / TOTALD;
    double var  = g_sumsq / TOTALD - mean * mean;
    double rstd = 1.0 / sqrt(var + EPSV);
    g_coef = (float)(-(double)gamma[0] * rstd / (double)TEMP);
}

// ---------------------------------------------------------------------------
// Kernel 4: in-place row softmax of coef*d. One 256-thread block per row.
// ---------------------------------------------------------------------------
__global__ __launch_bounds__(256)
void softmax_kernel(float* __restrict__ dout) {
    __shared__ float red[8];
    size_t base = (size_t)blockIdx.x * SEQ;
    float coef = g_coef;
    int tid = threadIdx.x;

    float4 v = *(float4*)(dout + base + tid * 4);
    float t0 = coef * v.x, t1 = coef * v.y, t2 = coef * v.z, t3 = coef * v.w;

    float m = fmaxf(fmaxf(t0, t1), fmaxf(t2, t3));
    #pragma unroll
    for (int o = 16; o > 0; o >>= 1) m = fmaxf(m, __shfl_xor_sync(0xffffffffu, m, o));
    if ((tid & 31) == 0) red[tid >> 5] = m;
    __syncthreads();
    float bm = red[0];
    #pragma unroll
    for (int i = 1; i < 8; i++) bm = fmaxf(bm, red[i]);

    float e0 = __expf(t0 - bm), e1 = __expf(t1 - bm);
    float e2 = __expf(t2 - bm), e3 = __expf(t3 - bm);
    float s = e0 + e1 + e2 + e3;
    #pragma unroll
    for (int o = 16; o > 0; o >>= 1) s += __shfl_xor_sync(0xffffffffu, s, o);
    __syncthreads();
    if ((tid & 31) == 0) red[tid >> 5] = s;
    __syncthreads();
    float bs = 0.f;
    #pragma unroll
    for (int i = 0; i < 8; i++) bs += red[i];
    float inv = 1.f / bs;

    *(float4*)(dout + base + tid * 4) =
        make_float4(e0 * inv, e1 * inv, e2 * inv, e3 * inv);
}

// ---------------------------------------------------------------------------
extern "C" void kernel_launch(void* const* d_in, const int* in_sizes, int n_in,
                              void* d_out, int out_size) {
    const float* x     = (const float*)d_in[0];
    const float* gamma = (const float*)d_in[1];
    float* out = (float*)d_out;

    cudaFuncSetAttribute(gram_tc_kernel,
                         cudaFuncAttributeMaxDynamicSharedMemorySize, GRAM_SMEM);

    conv_kernel<<<NROWS * 32 / 256, 256>>>(x);
    dim3 grid(SEQ / 128, SEQ / 128, BATCH);
    gram_tc_kernel<<<grid, 128, GRAM_SMEM>>>(out);
    finalize_kernel<<<1, 1>>>(gamma);
    softmax_kernel<<<NROWS, 256>>>(out);
}